// round 1
// baseline (speedup 1.0000x reference)
#include <cuda_runtime.h>
#include <math.h>

#define BB 32
#define CC 64
#define FH 80
#define FW 200
#define HW 16000           // FH*FW
#define LANES 64
#define SP 36
#define PE 78
#define J_TOT 2304         // SP*CC
#define M_TOT 2048         // BB*LANES

// ---------------- scratch (static __device__, per the allocation rules) -------------
__device__ float d_featT[BB * HW * CC];     // (B,H,W,C) transposed feature, 131 MB
__device__ float d_pool8[BB * 2000 * CC];   // partial pool: [b][q=h*25+w/8][c]
__device__ float d_xf[BB * CC * 250];       // pooled context [b][c][r]
__device__ float d_roi[M_TOT * J_TOT];      // [m=(b,lane)][j=s*64+cin]
__device__ float d_weff[J_TOT * CC];        // folded conv1d+fc weight [j][o]
__device__ float d_beff[CC];                // folded bias
__device__ float d_xp[M_TOT * CC];          // fc output [m][o]
__device__ float d_g[M_TOT * CC];           // attention output [m][c]

// ---------------- Kernel A: transpose (B,C,H,W)->(B,H,W,C) + fused pool partials ----
__global__ void kA_transpose_pool(const float* __restrict__ feat) {
    __shared__ float tile[32][33];
    __shared__ float qacc[4][32];
    int tx = threadIdx.x, ty = threadIdx.y;
    int bx = blockIdx.x, by = blockIdx.y, b = blockIdx.z;
    int hw = bx * 32 + tx;
    int cbase = by * 32;
#pragma unroll
    for (int i = 0; i < 4; i++) {
        int c = cbase + ty + i * 8;
        float v = feat[((size_t)(b * CC + c)) * HW + hw];
        tile[ty + i * 8][tx] = v;
        // partial pool over groups of 8 consecutive hw (exactly one q per 8 lanes)
        float s = v;
        s += __shfl_down_sync(0xffffffffu, s, 4);
        s += __shfl_down_sync(0xffffffffu, s, 2);
        s += __shfl_down_sync(0xffffffffu, s, 1);
        if ((tx & 7) == 0) qacc[tx >> 3][ty + i * 8] = s;  // unique (slot,c) writer
    }
    __syncthreads();
#pragma unroll
    for (int i = 0; i < 4; i++) {
        int hw2 = bx * 32 + ty + i * 8;
        int c2 = cbase + tx;
        d_featT[((size_t)b * HW + hw2) * CC + c2] = tile[tx][ty + i * 8];
    }
    int tid = ty * 32 + tx;
    if (tid < 128) {
        int slot = tid >> 5, cl = tid & 31;
        // q = hw/8 = h*25 + w/8 (exact since 8|200 and 8|32)
        d_pool8[((size_t)b * 2000 + bx * 4 + slot) * CC + cbase + cl] = qacc[slot][cl];
    }
}

// ---------------- Kernel A2: reduce 8 h-rows of pool8 -> d_xf[b][c][r] -------------
__global__ void kA2_pool_reduce() {
    int r = blockIdx.x;   // 0..249
    int b = blockIdx.y;
    int c = threadIdx.x;  // 64
    int rh = r / 25, rw = r - rh * 25;
    float acc = 0.f;
#pragma unroll
    for (int dh = 0; dh < 8; dh++)
        acc += d_pool8[((size_t)b * 2000 + (rh * 8 + dh) * 25 + rw) * CC + c];
    d_xf[((size_t)b * CC + c) * 250 + r] = acc * (1.0f / 64.0f);
}

// ---------------- Kernel B: 4-point gather from featT -> roi ------------------------
__global__ void kB_gather(const float* __restrict__ prior) {
    __shared__ int xcs[SP], xfs[SP], ycs[SP], yfs[SP];
    int m = blockIdx.x;  // b*64+lane
    int b = m >> 6;
    int tid = threadIdx.x;
    if (tid < SP) {
        int s = tid;
        float px = prior[(size_t)m * PE + 6 + 2 * s];
        float xs = fminf(px * 0.25f, 199.0f);
        xcs[s] = (int)ceilf(xs);
        xfs[s] = (int)floorf(xs);
        // prior_y computed in double to bit-match the Python float path, then f32
        double py = 319.0 - (320.0 / 71.0) * (double)(2 * s);
        float ys = fminf((float)py * 0.25f, 79.0f);
        ycs[s] = (int)ceilf(ys);
        yfs[s] = (int)floorf(ys);
    }
    __syncthreads();
    const float* fT = d_featT + (size_t)b * HW * CC;
    float* ro = d_roi + (size_t)m * J_TOT;
    for (int e = tid; e < J_TOT; e += 256) {
        int s = e >> 6, c = e & 63;
        int xc = xcs[s], xf = xfs[s], yc = ycs[s], yf = yfs[s];
        float v = fT[(yc * FW + xc) * CC + c] + fT[(yc * FW + xf) * CC + c]
                + fT[(yf * FW + xc) * CC + c] + fT[(yf * FW + xf) * CC + c];
        ro[e] = v * 0.25f;
    }
}

// ---------------- Kernel C: fold conv1d+fc -> W_eff [j][o], b_eff -------------------
__global__ void kC_fold(const float* __restrict__ w1, const float* __restrict__ b1,
                        const float* __restrict__ fw, const float* __restrict__ fb) {
    __shared__ float fc_s[2048];
    __shared__ float red[256];
    int o = blockIdx.x;
    int tid = threadIdx.x;
    for (int i = tid; i < 2048; i += 256) fc_s[i] = fw[o * 2048 + i];
    __syncthreads();

    // thread handles fixed cin = tid&63, s = tid>>6 + 4*it (9 its). W1 slice reused.
    int cin = tid & 63;
    int s0 = tid >> 6;
    float acc[9];
#pragma unroll
    for (int it = 0; it < 9; it++) acc[it] = 0.f;
    for (int cm = 0; cm < CC; cm++) {
        float wv[5];
#pragma unroll
        for (int k = 0; k < 5; k++) wv[k] = __ldg(w1 + (cm * CC + cin) * 5 + k);
        const float* frow = fc_s + cm * 32;
#pragma unroll
        for (int it = 0; it < 9; it++) {
            int s = s0 + it * 4;
#pragma unroll
            for (int k = 0; k < 5; k++) {
                int t = s - k;
                if ((unsigned)t < 32u) acc[it] += frow[t] * wv[k];
            }
        }
    }
#pragma unroll
    for (int it = 0; it < 9; it++) {
        int e = tid + it * 256;  // j = s*64+cin
        d_weff[(size_t)e * CC + o] = acc[it];
    }
    // b_eff[o] = fc_b[o] + sum fc_w[o, cm*32+t]*conv1d_b[cm]
    float p = 0.f;
    for (int i = tid; i < 2048; i += 256) p += fc_s[i] * b1[i >> 5];
    red[tid] = p;
    __syncthreads();
    for (int st = 128; st > 0; st >>= 1) {
        if (tid < st) red[tid] += red[tid + st];
        __syncthreads();
    }
    if (tid == 0) d_beff[o] = fb[o] + red[0];
}

// ---------------- Kernel D: x_p = roi (2048x2304) @ W_eff (2304x64) + b_eff ---------
// M=16 per block, j chunked 4x576 to keep smem < 48KB; thread = (o-pair, m-group).
__global__ void kD_xp() {
    __shared__ float rs[16 * 576];  // 36 KB
    int m0 = blockIdx.x * 16;
    int tid = threadIdx.x;
    int op = tid & 31;   // o pair: o0 = 2*op
    int o0 = op * 2;
    int mg = tid >> 5;   // 0..7; handles m = mg and mg+8
    float a00 = 0.f, a01 = 0.f, a10 = 0.f, a11 = 0.f;
    for (int ch = 0; ch < 4; ch++) {
        int jc = ch * 576;
        for (int i = tid; i < 16 * 576; i += 256) {
            int ml = i / 576;
            rs[i] = d_roi[(size_t)(m0 + ml) * J_TOT + jc + (i - ml * 576)];
        }
        __syncthreads();
        const float2* wp = (const float2*)(d_weff + (size_t)jc * CC) + op;
#pragma unroll 4
        for (int j = 0; j < 576; j++) {
            float2 w = wp[j * 32];
            float r0 = rs[mg * 576 + j];
            float r1 = rs[(mg + 8) * 576 + j];
            a00 += r0 * w.x; a01 += r0 * w.y;
            a10 += r1 * w.x; a11 += r1 * w.y;
        }
        __syncthreads();
    }
    float b0 = d_beff[o0], b1v = d_beff[o0 + 1];
    d_xp[(size_t)(m0 + mg) * CC + o0]         = a00 + b0;
    d_xp[(size_t)(m0 + mg) * CC + o0 + 1]     = a01 + b1v;
    d_xp[(size_t)(m0 + mg + 8) * CC + o0]     = a10 + b0;
    d_xp[(size_t)(m0 + mg + 8) * CC + o0 + 1] = a11 + b1v;
}

// ---------------- Kernel E: scores -> softmax -> g, one block per (b,lane) ----------
__global__ void kE_attn() {
    __shared__ float xp_s[64];
    __shared__ float w_s[256];
    __shared__ float red[256];
    int m = blockIdx.x, b = m >> 6;
    int tid = threadIdx.x;
    if (tid < 64) xp_s[tid] = d_xp[(size_t)m * CC + tid];
    __syncthreads();
    const float* xf = d_xf + (size_t)b * CC * 250;
    float sc = -INFINITY;
    if (tid < 250) {
        float a = 0.f;
#pragma unroll 8
        for (int c = 0; c < 64; c++) a += xp_s[c] * xf[c * 250 + tid];
        sc = a * 0.125f;  // / sqrt(64)
    }
    red[tid] = sc;
    __syncthreads();
    for (int st = 128; st > 0; st >>= 1) {
        if (tid < st) red[tid] = fmaxf(red[tid], red[tid + st]);
        __syncthreads();
    }
    float mx = red[0];
    __syncthreads();
    float ex = (tid < 250) ? expf(sc - mx) : 0.f;
    red[tid] = ex;
    __syncthreads();
    for (int st = 128; st > 0; st >>= 1) {
        if (tid < st) red[tid] += red[tid + st];
        __syncthreads();
    }
    float inv = 1.0f / red[0];
    w_s[tid] = ex * inv;
    __syncthreads();
    int warp = tid >> 5, lid = tid & 31;
    for (int c = warp; c < 64; c += 8) {
        float a = 0.f;
        for (int r = lid; r < 250; r += 32) a += w_s[r] * xf[c * 250 + r];
#pragma unroll
        for (int off = 16; off > 0; off >>= 1) a += __shfl_down_sync(0xffffffffu, a, off);
        if (lid == 0) d_g[(size_t)m * CC + c] = a;
    }
}

// ---------------- Kernel E3: conv1x1 + relu + residual add, one block per b ---------
__global__ void kE3_out(const float* __restrict__ w1x1, const float* __restrict__ b1x1,
                        const float* __restrict__ prior, float* __restrict__ out) {
    __shared__ float g_s[4096];
    __shared__ float gr_s[64];
    int b = blockIdx.x;
    int tid = threadIdx.x;
    for (int i = tid; i < 4096; i += 256) g_s[i] = d_g[(size_t)b * 4096 + i];
    __syncthreads();
    int warp = tid >> 5, lid = tid & 31;
    for (int o = warp; o < 64; o += 8) {
        const float* wr = w1x1 + (size_t)o * 4096;
        float a = 0.f;
        for (int j = lid; j < 4096; j += 32) a += g_s[j] * wr[j];
#pragma unroll
        for (int off = 16; off > 0; off >>= 1) a += __shfl_down_sync(0xffffffffu, a, off);
        if (lid == 0) gr_s[o] = fmaxf(a + b1x1[o], 0.f);
    }
    __syncthreads();
    for (int e = tid; e < 64 * PE; e += 256) {
        int j = e / PE;
        out[(size_t)b * 64 * PE + e] = gr_s[j] + prior[(size_t)b * 64 * PE + e];
    }
}

// ---------------- host launcher -----------------------------------------------------
extern "C" void kernel_launch(void* const* d_in, const int* in_sizes, int n_in,
                              void* d_out, int out_size) {
    const float* feature = (const float*)d_in[0];
    const float* prior   = (const float*)d_in[1];
    const float* w1      = (const float*)d_in[2];
    const float* b1      = (const float*)d_in[3];
    const float* fw      = (const float*)d_in[4];
    const float* fb      = (const float*)d_in[5];
    const float* w1x1    = (const float*)d_in[6];
    const float* b1x1    = (const float*)d_in[7];
    float* out = (float*)d_out;

    kA_transpose_pool<<<dim3(500, 2, BB), dim3(32, 8)>>>(feature);
    kA2_pool_reduce<<<dim3(250, BB), 64>>>();
    kB_gather<<<M_TOT, 256>>>(prior);
    kC_fold<<<CC, 256>>>(w1, b1, fw, fb);
    kD_xp<<<M_TOT / 16, 256>>>();
    kE_attn<<<M_TOT, 256>>>();
    kE3_out<<<BB, 256>>>(w1x1, b1x1, prior, out);
}

// round 2
// speedup vs baseline: 1.1249x; 1.1249x over previous
#include <cuda_runtime.h>
#include <cuda_fp16.h>
#include <math.h>

#define BB 32
#define CC 64
#define FH 80
#define FW 200
#define HW 16000
#define LANES 64
#define SP 36
#define PE 78
#define J_TOT 2304
#define M_TOT 2048

// ---------------- scratch ----------------
__device__ __half d_featT[BB * HW * CC];          // (B,H,W,C) fp16, 65.5 MB
__device__ float  d_pool8[BB * 2000 * CC];        // partial pool
__device__ float  d_xf[BB * CC * 250];            // pooled context [b][c][r]
__device__ float  d_weffp[8 * J_TOT * CC];        // fold partials [ck][j][o]
__device__ float  d_beffp[CC * 8];
__device__ float  d_weff[J_TOT * CC];             // folded weight [j][o]
__device__ float  d_beff[CC];
__device__ float  d_xp[M_TOT * CC];               // fc output [m][o]
__device__ float  d_g[M_TOT * CC];                // attention output [m][c]

__device__ __forceinline__ float warpMaxf(float a) {
#pragma unroll
    for (int off = 16; off > 0; off >>= 1) a = fmaxf(a, __shfl_xor_sync(0xffffffffu, a, off));
    return a;
}
__device__ __forceinline__ float warpSumf(float a) {
#pragma unroll
    for (int off = 16; off > 0; off >>= 1) a += __shfl_xor_sync(0xffffffffu, a, off);
    return a;
}

// ---------------- Kernel A: transpose (B,C,H,W)->(B,H,W,C) fp16 + fused pool --------
__global__ void kA_transpose_pool(const float* __restrict__ feat) {
    __shared__ float tile[32][33];
    __shared__ float qacc[4][32];
    int tx = threadIdx.x, ty = threadIdx.y;
    int bx = blockIdx.x, by = blockIdx.y, b = blockIdx.z;
    int hw = bx * 32 + tx;
    int cbase = by * 32;
#pragma unroll
    for (int i = 0; i < 4; i++) {
        int c = cbase + ty + i * 8;
        float v = feat[((size_t)(b * CC + c)) * HW + hw];
        tile[ty + i * 8][tx] = v;
        float s = v;
        s += __shfl_down_sync(0xffffffffu, s, 4);
        s += __shfl_down_sync(0xffffffffu, s, 2);
        s += __shfl_down_sync(0xffffffffu, s, 1);
        if ((tx & 7) == 0) qacc[tx >> 3][ty + i * 8] = s;
    }
    __syncthreads();
#pragma unroll
    for (int i = 0; i < 4; i++) {
        int hw2 = bx * 32 + ty + i * 8;
        int c2 = cbase + tx;
        d_featT[((size_t)b * HW + hw2) * CC + c2] = __float2half_rn(tile[tx][ty + i * 8]);
    }
    int tid = ty * 32 + tx;
    if (tid < 128) {
        int slot = tid >> 5, cl = tid & 31;
        d_pool8[((size_t)b * 2000 + bx * 4 + slot) * CC + cbase + cl] = qacc[slot][cl];
    }
}

// ---------------- Kernel A2: reduce 8 h-rows -> d_xf -------------------------------
__global__ void kA2_pool_reduce() {
    int r = blockIdx.x, b = blockIdx.y, c = threadIdx.x;
    int rh = r / 25, rw = r - rh * 25;
    float acc = 0.f;
#pragma unroll
    for (int dh = 0; dh < 8; dh++)
        acc += d_pool8[((size_t)b * 2000 + (rh * 8 + dh) * 25 + rw) * CC + c];
    d_xf[((size_t)b * CC + c) * 250 + r] = acc * (1.0f / 64.0f);
}

// ---------------- Kernel C: fold conv1d+fc (cm split in 8 chunks) ------------------
__global__ void kC_fold(const float* __restrict__ w1, const float* __restrict__ b1,
                        const float* __restrict__ fw) {
    __shared__ float fc_s[256];
    __shared__ float red[256];
    int o = blockIdx.x, ck = blockIdx.y;
    int cmBase = ck * 8;
    int tid = threadIdx.x;
    fc_s[tid] = fw[o * 2048 + cmBase * 32 + tid];
    __syncthreads();
    int cin = tid & 63, s0 = tid >> 6;
    float acc[9];
#pragma unroll
    for (int it = 0; it < 9; it++) acc[it] = 0.f;
#pragma unroll
    for (int cm8 = 0; cm8 < 8; cm8++) {
        int cm = cmBase + cm8;
        float wv[5];
#pragma unroll
        for (int k = 0; k < 5; k++) wv[k] = __ldg(w1 + (cm * CC + cin) * 5 + k);
        const float* frow = fc_s + cm8 * 32;
#pragma unroll
        for (int it = 0; it < 9; it++) {
            int s = s0 + it * 4;
#pragma unroll
            for (int k = 0; k < 5; k++) {
                int t = s - k;
                if ((unsigned)t < 32u) acc[it] += frow[t] * wv[k];
            }
        }
    }
#pragma unroll
    for (int it = 0; it < 9; it++)
        d_weffp[(size_t)ck * (J_TOT * CC) + (size_t)(tid + it * 256) * CC + o] = acc[it];
    // b_eff partial
    red[tid] = fc_s[tid] * b1[cmBase + (tid >> 5)];
    __syncthreads();
    for (int st = 128; st > 0; st >>= 1) {
        if (tid < st) red[tid] += red[tid + st];
        __syncthreads();
    }
    if (tid == 0) d_beffp[o * 8 + ck] = red[0];
}

// ---------------- Kernel C2: reduce fold partials ----------------------------------
__global__ void kC2_reduce(const float* __restrict__ fb) {
    int idx = blockIdx.x * 256 + threadIdx.x;  // < 147456
    float a = 0.f;
#pragma unroll
    for (int ck = 0; ck < 8; ck++) a += d_weffp[(size_t)ck * (J_TOT * CC) + idx];
    d_weff[idx] = a;
    if (blockIdx.x == 0 && threadIdx.x < CC) {
        int o = threadIdx.x;
        float s = 0.f;
#pragma unroll
        for (int ck = 0; ck < 8; ck++) s += d_beffp[o * 8 + ck];
        d_beff[o] = fb[o] + s;
    }
}

// ---------------- Kernel D: fused gather + x_p GEMM --------------------------------
// block = 16 m's. gather rs directly from fp16 featT, then rs @ W_eff.
__global__ void kD_xp(const float* __restrict__ prior) {
    __shared__ int xcs[16 * 36], xfs[16 * 36];
    __shared__ int ycs[36], yfs[36];
    __shared__ float rs[16 * 576];   // 36 KB
    int m0 = blockIdx.x * 16;
    int b = m0 >> 6;
    int tid = threadIdx.x;
    if (tid < 36) {
        double py = 319.0 - (320.0 / 71.0) * (double)(2 * tid);
        float ys = fminf((float)py * 0.25f, 79.0f);
        ycs[tid] = (int)ceilf(ys);
        yfs[tid] = (int)floorf(ys);
    }
    for (int i = tid; i < 576; i += 256) {
        int ml = i / 36, s = i - ml * 36;
        float px = prior[(size_t)(m0 + ml) * PE + 6 + 2 * s];
        float xs = fminf(px * 0.25f, 199.0f);
        xcs[i] = (int)ceilf(xs);
        xfs[i] = (int)floorf(xs);
    }
    __syncthreads();
    const __half* fT = d_featT + (size_t)b * HW * CC;
    int op = tid & 31, o0 = op * 2, mg = tid >> 5;
    float a00 = 0.f, a01 = 0.f, a10 = 0.f, a11 = 0.f;
    for (int ch = 0; ch < 4; ch++) {
        int jc = ch * 576, sBase = ch * 9;
#pragma unroll 1
        for (int ml = 0; ml < 16; ml++) {
            for (int jj = tid; jj < 576; jj += 256) {
                int sl = jj >> 6, c = jj & 63;
                int s = sBase + sl;
                int xc = xcs[ml * 36 + s], xf_ = xfs[ml * 36 + s];
                int yc = ycs[s], yf_ = yfs[s];
                float v = __half2float(fT[(yc * FW + xc) * CC + c])
                        + __half2float(fT[(yc * FW + xf_) * CC + c])
                        + __half2float(fT[(yf_ * FW + xc) * CC + c])
                        + __half2float(fT[(yf_ * FW + xf_) * CC + c]);
                rs[ml * 576 + jj] = v * 0.25f;
            }
        }
        __syncthreads();
        const float2* wp = (const float2*)(d_weff + (size_t)jc * CC) + op;
#pragma unroll 4
        for (int j = 0; j < 576; j++) {
            float2 w = wp[j * 32];
            float r0 = rs[mg * 576 + j];
            float r1 = rs[(mg + 8) * 576 + j];
            a00 += r0 * w.x; a01 += r0 * w.y;
            a10 += r1 * w.x; a11 += r1 * w.y;
        }
        __syncthreads();
    }
    float b0 = d_beff[o0], b1v = d_beff[o0 + 1];
    d_xp[(size_t)(m0 + mg) * CC + o0]         = a00 + b0;
    d_xp[(size_t)(m0 + mg) * CC + o0 + 1]     = a01 + b1v;
    d_xp[(size_t)(m0 + mg + 8) * CC + o0]     = a10 + b0;
    d_xp[(size_t)(m0 + mg + 8) * CC + o0 + 1] = a11 + b1v;
}

// ---------------- Kernel E: attention, xf cached in smem, warp-per-lane ------------
__global__ void kE_attn() {
    extern __shared__ float xf_s[];          // 64*250 floats = 64000 B
    __shared__ float xp_s[8 * 64];
    __shared__ float g_buf[8 * 64];
    int b = blockIdx.x, lg = blockIdx.y;
    int tid = threadIdx.x, w = tid >> 5, lid = tid & 31;
    const float4* src = (const float4*)(d_xf + (size_t)b * (CC * 250));
    for (int i = tid; i < 4000; i += 256) ((float4*)xf_s)[i] = src[i];
    for (int i = tid; i < 512; i += 256) {
        int lane = i >> 6, c = i & 63;
        xp_s[i] = d_xp[(size_t)(b * 64 + lg * 8 + lane) * CC + c];
    }
    __syncthreads();

    int m = b * 64 + lg * 8 + w;
    const float* xpw = xp_s + w * 64;
    float sc[8];
#pragma unroll
    for (int k = 0; k < 8; k++) {
        int r = lid + 32 * k;
        if (r < 250) {
            float a = 0.f;
#pragma unroll 8
            for (int c = 0; c < 64; c++) a += xpw[c] * xf_s[c * 250 + r];
            sc[k] = a * 0.125f;
        } else sc[k] = -INFINITY;
    }
    float mx = fmaxf(fmaxf(fmaxf(sc[0], sc[1]), fmaxf(sc[2], sc[3])),
                     fmaxf(fmaxf(sc[4], sc[5]), fmaxf(sc[6], sc[7])));
    mx = warpMaxf(mx);
    float wsum = 0.f;
    float wgt[8];
#pragma unroll
    for (int k = 0; k < 8; k++) {
        int r = lid + 32 * k;
        wgt[k] = (r < 250) ? expf(sc[k] - mx) : 0.f;
        wsum += wgt[k];
    }
    wsum = warpSumf(wsum);
    float inv = 1.0f / wsum;
#pragma unroll
    for (int k = 0; k < 8; k++) wgt[k] *= inv;

    for (int c = 0; c < 64; c++) {
        float a = 0.f;
#pragma unroll
        for (int k = 0; k < 8; k++) {
            int r = lid + 32 * k;
            if (r < 250) a += wgt[k] * xf_s[c * 250 + r];
        }
        a = warpSumf(a);
        if (lid == 0) g_buf[w * 64 + c] = a;
    }
    __syncthreads();
    for (int i = tid; i < 512; i += 256) {
        int lane = i >> 6, c = i & 63;
        d_g[(size_t)(b * 64 + lg * 8 + lane) * CC + c] = g_buf[i];
    }
}

// ---------------- Kernel E3: conv1x1 + relu + residual, per (b, o-group) -----------
__global__ void kE3_out(const float* __restrict__ w1x1, const float* __restrict__ b1x1,
                        const float* __restrict__ prior, float* __restrict__ out) {
    __shared__ float g_s[4096];
    __shared__ float gr_s[8];
    int b = blockIdx.x, og = blockIdx.y;
    int tid = threadIdx.x, w = tid >> 5, lid = tid & 31;
    const float4* gsrc = (const float4*)(d_g + (size_t)b * 4096);
    for (int i = tid; i < 1024; i += 256) ((float4*)g_s)[i] = gsrc[i];
    __syncthreads();
    int o = og * 8 + w;
    const float4* wr = (const float4*)(w1x1 + (size_t)o * 4096);
    float a = 0.f;
#pragma unroll 4
    for (int j4 = lid; j4 < 1024; j4 += 32) {
        float4 wv = wr[j4];
        float4 gv = ((const float4*)g_s)[j4];
        a += wv.x * gv.x + wv.y * gv.y + wv.z * gv.z + wv.w * gv.w;
    }
    a = warpSumf(a);
    if (lid == 0) gr_s[w] = fmaxf(a + b1x1[o], 0.f);
    __syncthreads();
    for (int e = tid; e < 8 * PE; e += 256) {
        int jl = e / PE, t = e - jl * PE;
        size_t idx = (size_t)b * (64 * PE) + (size_t)(og * 8 + jl) * PE + t;
        out[idx] = gr_s[jl] + prior[idx];
    }
}

// ---------------- host launcher ----------------------------------------------------
extern "C" void kernel_launch(void* const* d_in, const int* in_sizes, int n_in,
                              void* d_out, int out_size) {
    const float* feature = (const float*)d_in[0];
    const float* prior   = (const float*)d_in[1];
    const float* w1      = (const float*)d_in[2];
    const float* b1      = (const float*)d_in[3];
    const float* fw      = (const float*)d_in[4];
    const float* fb      = (const float*)d_in[5];
    const float* w1x1    = (const float*)d_in[6];
    const float* b1x1    = (const float*)d_in[7];
    float* out = (float*)d_out;

    cudaFuncSetAttribute(kE_attn, cudaFuncAttributeMaxDynamicSharedMemorySize, 64000);

    kA_transpose_pool<<<dim3(500, 2, BB), dim3(32, 8)>>>(feature);
    kA2_pool_reduce<<<dim3(250, BB), 64>>>();
    kC_fold<<<dim3(CC, 8), 256>>>(w1, b1, fw);
    kC2_reduce<<<576, 256>>>(fb);
    kD_xp<<<M_TOT / 16, 256>>>(prior);
    kE_attn<<<dim3(BB, 8), 256, 64000>>>();
    kE3_out<<<dim3(BB, 8), 256>>>(w1x1, b1x1, prior, out);
}

// round 3
// speedup vs baseline: 2.1472x; 1.9088x over previous
#include <cuda_runtime.h>
#include <cuda_fp16.h>
#include <mma.h>
#include <math.h>

using namespace nvcuda;

#define BB 32
#define CC 64
#define FH 80
#define FW 200
#define HW 16000
#define LANES 64
#define SP 36
#define PE 78
#define J_TOT 2304
#define M_TOT 2048

// ---------------- scratch ----------------
__device__ __half d_featT[BB * HW * CC];          // (B,H,W,C) fp16
__device__ float  d_pool8[BB * 2000 * CC];        // partial pool
__device__ float  d_xf[BB * CC * 250];            // pooled context [b][c][r]
__device__ float  d_weffp[8 * CC * J_TOT];        // fold partials [ck][o][j]
__device__ float  d_beffp[CC * 8];
__device__ __half d_weffh[J_TOT * CC];            // folded weight fp16 [j][o]
__device__ float  d_beff[CC];
__device__ float  d_xp[M_TOT * CC];               // fc output [m][o]
__device__ float  d_g[M_TOT * CC];                // attention output [m][c]

__device__ __forceinline__ float warpMaxf(float a) {
#pragma unroll
    for (int off = 16; off > 0; off >>= 1) a = fmaxf(a, __shfl_xor_sync(0xffffffffu, a, off));
    return a;
}
__device__ __forceinline__ float warpSumf(float a) {
#pragma unroll
    for (int off = 16; off > 0; off >>= 1) a += __shfl_xor_sync(0xffffffffu, a, off);
    return a;
}

// ---------------- Kernel A: transpose (B,C,H,W)->(B,H,W,C) fp16 + fused pool --------
__global__ void kA_transpose_pool(const float* __restrict__ feat) {
    __shared__ float tile[32][33];
    __shared__ float qacc[4][32];
    int tx = threadIdx.x, ty = threadIdx.y;
    int bx = blockIdx.x, by = blockIdx.y, b = blockIdx.z;
    int hw = bx * 32 + tx;
    int cbase = by * 32;
#pragma unroll
    for (int i = 0; i < 4; i++) {
        int c = cbase + ty + i * 8;
        float v = feat[((size_t)(b * CC + c)) * HW + hw];
        tile[ty + i * 8][tx] = v;
        float s = v;
        s += __shfl_down_sync(0xffffffffu, s, 4);
        s += __shfl_down_sync(0xffffffffu, s, 2);
        s += __shfl_down_sync(0xffffffffu, s, 1);
        if ((tx & 7) == 0) qacc[tx >> 3][ty + i * 8] = s;
    }
    __syncthreads();
#pragma unroll
    for (int i = 0; i < 4; i++) {
        int hw2 = bx * 32 + ty + i * 8;
        int c2 = cbase + tx;
        d_featT[((size_t)b * HW + hw2) * CC + c2] = __float2half_rn(tile[tx][ty + i * 8]);
    }
    int tid = ty * 32 + tx;
    if (tid < 128) {
        int slot = tid >> 5, cl = tid & 31;
        d_pool8[((size_t)b * 2000 + bx * 4 + slot) * CC + cbase + cl] = qacc[slot][cl];
    }
}

// ---------------- Kernel A2: reduce 8 h-rows -> d_xf -------------------------------
__global__ void kA2_pool_reduce() {
    int r = blockIdx.x, b = blockIdx.y, c = threadIdx.x;
    int rh = r / 25, rw = r - rh * 25;
    float acc = 0.f;
#pragma unroll
    for (int dh = 0; dh < 8; dh++)
        acc += d_pool8[((size_t)b * 2000 + (rh * 8 + dh) * 25 + rw) * CC + c];
    d_xf[((size_t)b * CC + c) * 250 + r] = acc * (1.0f / 64.0f);
}

// ---------------- Kernel C: fold conv1d+fc partials, layout [ck][o][j] -------------
__global__ void kC_fold(const float* __restrict__ w1, const float* __restrict__ b1,
                        const float* __restrict__ fw) {
    __shared__ float fc_s[256];
    __shared__ float red[256];
    int o = blockIdx.x, ck = blockIdx.y;
    int cmBase = ck * 8;
    int tid = threadIdx.x;
    fc_s[tid] = fw[o * 2048 + cmBase * 32 + tid];
    __syncthreads();
    int cin = tid & 63, s0 = tid >> 6;
    float acc[9];
#pragma unroll
    for (int it = 0; it < 9; it++) acc[it] = 0.f;
#pragma unroll
    for (int cm8 = 0; cm8 < 8; cm8++) {
        int cm = cmBase + cm8;
        float wv[5];
#pragma unroll
        for (int k = 0; k < 5; k++) wv[k] = __ldg(w1 + (cm * CC + cin) * 5 + k);
        const float* frow = fc_s + cm8 * 32;
#pragma unroll
        for (int it = 0; it < 9; it++) {
            int s = s0 + it * 4;
#pragma unroll
            for (int k = 0; k < 5; k++) {
                int t = s - k;
                if ((unsigned)t < 32u) acc[it] += frow[t] * wv[k];
            }
        }
    }
#pragma unroll
    for (int it = 0; it < 9; it++)
        d_weffp[(size_t)ck * (CC * J_TOT) + (size_t)o * J_TOT + (tid + it * 256)] = acc[it];
    red[tid] = fc_s[tid] * b1[cmBase + (tid >> 5)];
    __syncthreads();
    for (int st = 128; st > 0; st >>= 1) {
        if (tid < st) red[tid] += red[tid + st];
        __syncthreads();
    }
    if (tid == 0) d_beffp[o * 8 + ck] = red[0];
}

// ---------------- Kernel C2: reduce partials + transpose -> fp16 [j][o] ------------
__global__ void kC2_reduce(const float* __restrict__ fb) {
    __shared__ float t_s[64][65];
    int jb = blockIdx.x;           // 36 j-tiles of 64
    int tid = threadIdx.x;
    for (int i = tid; i < 4096; i += 256) {
        int o = i >> 6, jl = i & 63;
        int j = jb * 64 + jl;
        float a = 0.f;
#pragma unroll
        for (int ck = 0; ck < 8; ck++)
            a += d_weffp[(size_t)ck * (CC * J_TOT) + (size_t)o * J_TOT + j];
        t_s[jl][o] = a;
    }
    __syncthreads();
    for (int i = tid; i < 2048; i += 256) {
        int jl = i >> 5, op = i & 31;
        __half2 h = __floats2half2_rn(t_s[jl][2 * op], t_s[jl][2 * op + 1]);
        ((__half2*)d_weffh)[(size_t)(jb * 64 + jl) * 32 + op] = h;
    }
    if (jb == 0 && tid < CC) {
        float s = 0.f;
#pragma unroll
        for (int ck = 0; ck < 8; ck++) s += d_beffp[tid * 8 + ck];
        d_beff[tid] = fb[tid] + s;
    }
}

// ---------------- Kernel D: fused gather(fp16) + wmma GEMM -> x_p ------------------
// block = 16 m's, 256 threads. rs = [16][2304] fp16 in dyn smem; 8 warps wmma (4 o-tiles x 2 k-halves).
__global__ void kD_xp(const float* __restrict__ prior) {
    extern __shared__ char smraw[];
    __half* rs = (__half*)smraw;                       // 16*2304*2 = 73728 B
    float* part = (float*)(smraw + 16 * 2304 * 2);     // 8*256 floats = 8192 B
    __shared__ int offs0[576], offs1[576], offs2[576], offs3[576];

    int m0 = blockIdx.x * 16;
    int b = m0 >> 6;
    int tid = threadIdx.x;
    int w = tid >> 5, lane = tid & 31;

    // coordinates -> 4 point base offsets per (ml, s)
    for (int i = tid; i < 576; i += 256) {
        int ml = i / 36, s = i - ml * 36;
        float px = prior[(size_t)(m0 + ml) * PE + 6 + 2 * s];
        float xs = fminf(px * 0.25f, 199.0f);
        int xc = (int)ceilf(xs), xf_ = (int)floorf(xs);
        double py = 319.0 - (320.0 / 71.0) * (double)(2 * s);
        float ys = fminf((float)py * 0.25f, 79.0f);
        int yc = (int)ceilf(ys), yf_ = (int)floorf(ys);
        offs0[i] = (yc * FW + xc) * CC;
        offs1[i] = (yc * FW + xf_) * CC;
        offs2[i] = (yf_ * FW + xc) * CC;
        offs3[i] = (yf_ * FW + xf_) * CC;
    }
    __syncthreads();

    // gather: warp per point-quad, lane = channel-pair (half2)
    const __half2* f2 = (const __half2*)(d_featT + (size_t)b * HW * CC);
    __half2* rs2 = (__half2*)rs;
    for (int i = w; i < 576; i += 8) {
        int ml = i / 36, s = i - ml * 36;
        float2 v0 = __half22float2(f2[(offs0[i] >> 1) + lane]);
        float2 v1 = __half22float2(f2[(offs1[i] >> 1) + lane]);
        float2 v2 = __half22float2(f2[(offs2[i] >> 1) + lane]);
        float2 v3 = __half22float2(f2[(offs3[i] >> 1) + lane]);
        float2 r;
        r.x = (v0.x + v1.x + v2.x + v3.x) * 0.25f;
        r.y = (v0.y + v1.y + v2.y + v3.y) * 0.25f;
        rs2[((ml * J_TOT + s * CC) >> 1) + lane] = __float22half2_rn(r);
    }
    __syncthreads();

    // wmma: warp w -> otile = w>>1 (16 o's), khalf = w&1 (72 of 144 k-steps)
    {
        int otile = w >> 1, kh = w & 1;
        wmma::fragment<wmma::matrix_a, 16, 16, 16, __half, wmma::row_major> af;
        wmma::fragment<wmma::matrix_b, 16, 16, 16, __half, wmma::row_major> bf;
        wmma::fragment<wmma::accumulator, 16, 16, 16, float> cf;
        wmma::fill_fragment(cf, 0.0f);
        for (int ks = kh * 72; ks < kh * 72 + 72; ks++) {
            int k0 = ks * 16;
            wmma::load_matrix_sync(af, rs + k0, J_TOT);
            wmma::load_matrix_sync(bf, d_weffh + (size_t)k0 * CC + otile * 16, CC);
            wmma::mma_sync(cf, af, bf, cf);
        }
        wmma::store_matrix_sync(part + w * 256, cf, 16, wmma::mem_row_major);
    }
    __syncthreads();

    for (int i = tid; i < 1024; i += 256) {
        int m = i >> 6, o = i & 63;
        int ot = o >> 4, ol = o & 15;
        float v = part[(ot * 2) * 256 + m * 16 + ol]
                + part[(ot * 2 + 1) * 256 + m * 16 + ol] + d_beff[o];
        d_xp[(size_t)(m0 + m) * CC + o] = v;
    }
}

// ---------------- Kernel E: attention, xf cached in smem, warp-per-lane ------------
__global__ void kE_attn() {
    extern __shared__ float xf_s[];          // 64*250 floats = 64000 B
    __shared__ float xp_s[8 * 64];
    __shared__ float g_buf[8 * 64];
    int b = blockIdx.x, lg = blockIdx.y;
    int tid = threadIdx.x, w = tid >> 5, lid = tid & 31;
    const float4* src = (const float4*)(d_xf + (size_t)b * (CC * 250));
    for (int i = tid; i < 4000; i += 256) ((float4*)xf_s)[i] = src[i];
    for (int i = tid; i < 512; i += 256) {
        int lane = i >> 6, c = i & 63;
        xp_s[i] = d_xp[(size_t)(b * 64 + lg * 8 + lane) * CC + c];
    }
    __syncthreads();

    const float* xpw = xp_s + w * 64;
    float sc[8];
#pragma unroll
    for (int k = 0; k < 8; k++) {
        int r = lid + 32 * k;
        if (r < 250) {
            float a = 0.f;
#pragma unroll 8
            for (int c = 0; c < 64; c++) a += xpw[c] * xf_s[c * 250 + r];
            sc[k] = a * 0.125f;
        } else sc[k] = -INFINITY;
    }
    float mx = fmaxf(fmaxf(fmaxf(sc[0], sc[1]), fmaxf(sc[2], sc[3])),
                     fmaxf(fmaxf(sc[4], sc[5]), fmaxf(sc[6], sc[7])));
    mx = warpMaxf(mx);
    float wsum = 0.f;
    float wgt[8];
#pragma unroll
    for (int k = 0; k < 8; k++) {
        int r = lid + 32 * k;
        wgt[k] = (r < 250) ? expf(sc[k] - mx) : 0.f;
        wsum += wgt[k];
    }
    wsum = warpSumf(wsum);
    float inv = 1.0f / wsum;
#pragma unroll
    for (int k = 0; k < 8; k++) wgt[k] *= inv;

    for (int c = 0; c < 64; c++) {
        float a = 0.f;
#pragma unroll
        for (int k = 0; k < 8; k++) {
            int r = lid + 32 * k;
            if (r < 250) a += wgt[k] * xf_s[c * 250 + r];
        }
        a = warpSumf(a);
        if (lid == 0) g_buf[w * 64 + c] = a;
    }
    __syncthreads();
    for (int i = tid; i < 512; i += 256) {
        int lane = i >> 6, c = i & 63;
        d_g[(size_t)(b * 64 + lg * 8 + lane) * CC + c] = g_buf[i];
    }
}

// ---------------- Kernel E3: conv1x1 + relu + residual, per (b, o-group) -----------
__global__ void kE3_out(const float* __restrict__ w1x1, const float* __restrict__ b1x1,
                        const float* __restrict__ prior, float* __restrict__ out) {
    __shared__ float g_s[4096];
    __shared__ float gr_s[8];
    int b = blockIdx.x, og = blockIdx.y;
    int tid = threadIdx.x, w = tid >> 5, lid = tid & 31;
    const float4* gsrc = (const float4*)(d_g + (size_t)b * 4096);
    for (int i = tid; i < 1024; i += 256) ((float4*)g_s)[i] = gsrc[i];
    __syncthreads();
    int o = og * 8 + w;
    const float4* wr = (const float4*)(w1x1 + (size_t)o * 4096);
    float a = 0.f;
#pragma unroll 4
    for (int j4 = lid; j4 < 1024; j4 += 32) {
        float4 wv = wr[j4];
        float4 gv = ((const float4*)g_s)[j4];
        a += wv.x * gv.x + wv.y * gv.y + wv.z * gv.z + wv.w * gv.w;
    }
    a = warpSumf(a);
    if (lid == 0) gr_s[w] = fmaxf(a + b1x1[o], 0.f);
    __syncthreads();
    for (int e = tid; e < 8 * PE; e += 256) {
        int jl = e / PE, t = e - jl * PE;
        size_t idx = (size_t)b * (64 * PE) + (size_t)(og * 8 + jl) * PE + t;
        out[idx] = gr_s[jl] + prior[idx];
    }
}

// ---------------- host launcher ----------------------------------------------------
extern "C" void kernel_launch(void* const* d_in, const int* in_sizes, int n_in,
                              void* d_out, int out_size) {
    const float* feature = (const float*)d_in[0];
    const float* prior   = (const float*)d_in[1];
    const float* w1      = (const float*)d_in[2];
    const float* b1      = (const float*)d_in[3];
    const float* fw      = (const float*)d_in[4];
    const float* fb      = (const float*)d_in[5];
    const float* w1x1    = (const float*)d_in[6];
    const float* b1x1    = (const float*)d_in[7];
    float* out = (float*)d_out;

    cudaFuncSetAttribute(kD_xp, cudaFuncAttributeMaxDynamicSharedMemorySize, 16 * 2304 * 2 + 8192);
    cudaFuncSetAttribute(kE_attn, cudaFuncAttributeMaxDynamicSharedMemorySize, 64000);

    kA_transpose_pool<<<dim3(500, 2, BB), dim3(32, 8)>>>(feature);
    kA2_pool_reduce<<<dim3(250, BB), 64>>>();
    kC_fold<<<dim3(CC, 8), 256>>>(w1, b1, fw);
    kC2_reduce<<<36, 256>>>(fb);
    kD_xp<<<M_TOT / 16, 256, 16 * 2304 * 2 + 8192>>>(prior);
    kE_attn<<<dim3(BB, 8), 256, 64000>>>();
    kE3_out<<<dim3(BB, 8), 256>>>(w1x1, b1x1, prior, out);
}

// round 4
// speedup vs baseline: 2.5650x; 1.1946x over previous
#include <cuda_runtime.h>
#include <cuda_fp16.h>
#include <mma.h>
#include <math.h>

using namespace nvcuda;

#define BB 32
#define CC 64
#define FH 80
#define FW 200
#define HW 16000
#define LANES 64
#define SP 36
#define PE 78
#define J_TOT 2304
#define M_TOT 2048

// ---------------- scratch ----------------
__device__ __half d_featT[BB * HW * CC];          // (B,H,W,C) fp16
__device__ float  d_pool8[BB * 2000 * CC];        // partial pool
__device__ __half d_xfh[BB * CC * 250];           // pooled context fp16 [b][c][r]
__device__ float  d_weffp[8 * CC * J_TOT];        // fold partials [ck][o][j]
__device__ float  d_beffp[CC * 8];
__device__ __half d_weffh[J_TOT * CC];            // folded weight fp16 [j][o]
__device__ float  d_beff[CC];
__device__ float  d_xp[M_TOT * CC];               // fc output [m][o]
__device__ float  d_g[M_TOT * CC];                // attention output [m][c]

__device__ __forceinline__ float warpMaxf(float a) {
#pragma unroll
    for (int off = 16; off > 0; off >>= 1) a = fmaxf(a, __shfl_xor_sync(0xffffffffu, a, off));
    return a;
}
__device__ __forceinline__ float warpSumf(float a) {
#pragma unroll
    for (int off = 16; off > 0; off >>= 1) a += __shfl_xor_sync(0xffffffffu, a, off);
    return a;
}

// ---------------- Kernel A: transpose (B,C,H,W)->(B,H,W,C) fp16 + fused pool --------
__global__ void kA_transpose_pool(const float* __restrict__ feat) {
    __shared__ float tile[32][33];
    __shared__ float qacc[4][32];
    int tx = threadIdx.x, ty = threadIdx.y;
    int bx = blockIdx.x, by = blockIdx.y, b = blockIdx.z;
    int hw = bx * 32 + tx;
    int cbase = by * 32;
#pragma unroll
    for (int i = 0; i < 4; i++) {
        int c = cbase + ty + i * 8;
        float v = feat[((size_t)(b * CC + c)) * HW + hw];
        tile[ty + i * 8][tx] = v;
        float s = v;
        s += __shfl_down_sync(0xffffffffu, s, 4);
        s += __shfl_down_sync(0xffffffffu, s, 2);
        s += __shfl_down_sync(0xffffffffu, s, 1);
        if ((tx & 7) == 0) qacc[tx >> 3][ty + i * 8] = s;
    }
    __syncthreads();
    int tid = ty * 32 + tx;
#pragma unroll
    for (int it = 0; it < 2; it++) {
        int idx = tid + it * 256;        // 0..511
        int row = idx >> 4;              // hw-local 0..31
        int pr  = idx & 15;              // c-pair 0..15
        __half2 h = __floats2half2_rn(tile[2 * pr][row], tile[2 * pr + 1][row]);
        ((__half2*)(d_featT + ((size_t)b * HW + bx * 32 + row) * CC + cbase))[pr] = h;
    }
    if (tid < 128) {
        int slot = tid >> 5, cl = tid & 31;
        d_pool8[((size_t)b * 2000 + bx * 4 + slot) * CC + cbase + cl] = qacc[slot][cl];
    }
}

// ---------------- Kernel A2: reduce 8 h-rows -> d_xfh (fp16) -----------------------
__global__ void kA2_pool_reduce() {
    int r = blockIdx.x, b = blockIdx.y, c = threadIdx.x;
    int rh = r / 25, rw = r - rh * 25;
    float acc = 0.f;
#pragma unroll
    for (int dh = 0; dh < 8; dh++)
        acc += d_pool8[((size_t)b * 2000 + (rh * 8 + dh) * 25 + rw) * CC + c];
    d_xfh[((size_t)b * CC + c) * 250 + r] = __float2half_rn(acc * (1.0f / 64.0f));
}

// ---------------- Kernel C: fold conv1d+fc partials, layout [ck][o][j] -------------
__global__ void kC_fold(const float* __restrict__ w1, const float* __restrict__ b1,
                        const float* __restrict__ fw) {
    __shared__ float fc_s[256];
    __shared__ float red[256];
    int o = blockIdx.x, ck = blockIdx.y;
    int cmBase = ck * 8;
    int tid = threadIdx.x;
    fc_s[tid] = fw[o * 2048 + cmBase * 32 + tid];
    __syncthreads();
    int cin = tid & 63, s0 = tid >> 6;
    float acc[9];
#pragma unroll
    for (int it = 0; it < 9; it++) acc[it] = 0.f;
#pragma unroll
    for (int cm8 = 0; cm8 < 8; cm8++) {
        int cm = cmBase + cm8;
        float wv[5];
#pragma unroll
        for (int k = 0; k < 5; k++) wv[k] = __ldg(w1 + (cm * CC + cin) * 5 + k);
        const float* frow = fc_s + cm8 * 32;
#pragma unroll
        for (int it = 0; it < 9; it++) {
            int s = s0 + it * 4;
#pragma unroll
            for (int k = 0; k < 5; k++) {
                int t = s - k;
                if ((unsigned)t < 32u) acc[it] += frow[t] * wv[k];
            }
        }
    }
#pragma unroll
    for (int it = 0; it < 9; it++)
        d_weffp[(size_t)ck * (CC * J_TOT) + (size_t)o * J_TOT + (tid + it * 256)] = acc[it];
    red[tid] = fc_s[tid] * b1[cmBase + (tid >> 5)];
    __syncthreads();
    for (int st = 128; st > 0; st >>= 1) {
        if (tid < st) red[tid] += red[tid + st];
        __syncthreads();
    }
    if (tid == 0) d_beffp[o * 8 + ck] = red[0];
}

// ---------------- Kernel C2: reduce partials + transpose -> fp16 [j][o] ------------
// grid (36 jb, 8 og); block handles 64 j x 8 o.
__global__ void kC2_reduce(const float* __restrict__ fb) {
    __shared__ float t_s[64][9];
    int jb = blockIdx.x, og = blockIdx.y;
    int tid = threadIdx.x;
#pragma unroll
    for (int i = tid; i < 512; i += 256) {
        int ol = i >> 6, jl = i & 63;
        float a = 0.f;
#pragma unroll
        for (int ck = 0; ck < 8; ck++)
            a += d_weffp[(size_t)ck * (CC * J_TOT) + (size_t)(og * 8 + ol) * J_TOT + jb * 64 + jl];
        t_s[jl][ol] = a;
    }
    __syncthreads();
    {
        int jl = tid >> 2, op = tid & 3;
        __half2 h = __floats2half2_rn(t_s[jl][2 * op], t_s[jl][2 * op + 1]);
        ((__half2*)d_weffh)[(size_t)(jb * 64 + jl) * 32 + og * 4 + op] = h;
    }
    if (jb == 0 && og == 0 && tid < CC) {
        float s = 0.f;
#pragma unroll
        for (int ck = 0; ck < 8; ck++) s += d_beffp[tid * 8 + ck];
        d_beff[tid] = fb[tid] + s;
    }
}

// ---------------- Kernel D: fused gather(fp16) + wmma GEMM -> x_p ------------------
// 512 threads, 16 warps: otile(4) x kquarter(4). 16 m's per block.
__global__ void kD_xp(const float* __restrict__ prior) {
    extern __shared__ char smraw[];
    __half* rs = (__half*)smraw;                       // 16*2304*2 = 73728 B
    float* part = (float*)(smraw + 16 * 2304 * 2);     // 16*256 floats = 16384 B
    __shared__ int offs0[576], offs1[576], offs2[576], offs3[576];

    int m0 = blockIdx.x * 16;
    int b = m0 >> 6;
    int tid = threadIdx.x;
    int w = tid >> 5, lane = tid & 31;

    for (int i = tid; i < 576; i += 512) {
        int ml = i / 36, s = i - ml * 36;
        float px = prior[(size_t)(m0 + ml) * PE + 6 + 2 * s];
        float xs = fminf(px * 0.25f, 199.0f);
        int xc = (int)ceilf(xs), xf_ = (int)floorf(xs);
        double py = 319.0 - (320.0 / 71.0) * (double)(2 * s);
        float ys = fminf((float)py * 0.25f, 79.0f);
        int yc = (int)ceilf(ys), yf_ = (int)floorf(ys);
        offs0[i] = (yc * FW + xc) * CC;
        offs1[i] = (yc * FW + xf_) * CC;
        offs2[i] = (yf_ * FW + xc) * CC;
        offs3[i] = (yf_ * FW + xf_) * CC;
    }
    __syncthreads();

    const __half2* f2 = (const __half2*)(d_featT + (size_t)b * HW * CC);
    __half2* rs2 = (__half2*)rs;
#pragma unroll 2
    for (int i = w; i < 576; i += 16) {
        int ml = i / 36, s = i - ml * 36;
        float2 v0 = __half22float2(f2[(offs0[i] >> 1) + lane]);
        float2 v1 = __half22float2(f2[(offs1[i] >> 1) + lane]);
        float2 v2 = __half22float2(f2[(offs2[i] >> 1) + lane]);
        float2 v3 = __half22float2(f2[(offs3[i] >> 1) + lane]);
        float2 r;
        r.x = (v0.x + v1.x + v2.x + v3.x) * 0.25f;
        r.y = (v0.y + v1.y + v2.y + v3.y) * 0.25f;
        rs2[((ml * J_TOT + s * CC) >> 1) + lane] = __float22half2_rn(r);
    }
    __syncthreads();

    {
        int otile = w >> 2, kq = w & 3;   // 4 o-tiles x 4 k-quarters (36 ksteps each)
        wmma::fragment<wmma::matrix_a, 16, 16, 16, __half, wmma::row_major> af;
        wmma::fragment<wmma::matrix_b, 16, 16, 16, __half, wmma::row_major> bf;
        wmma::fragment<wmma::accumulator, 16, 16, 16, float> cf;
        wmma::fill_fragment(cf, 0.0f);
        for (int ks = kq * 36; ks < kq * 36 + 36; ks++) {
            int k0 = ks * 16;
            wmma::load_matrix_sync(af, rs + k0, J_TOT);
            wmma::load_matrix_sync(bf, d_weffh + (size_t)k0 * CC + otile * 16, CC);
            wmma::mma_sync(cf, af, bf, cf);
        }
        wmma::store_matrix_sync(part + w * 256, cf, 16, wmma::mem_row_major);
    }
    __syncthreads();

    for (int i = tid; i < 1024; i += 512) {
        int m = i >> 6, o = i & 63;
        int ot = o >> 4, ol = o & 15;
        float v = part[(ot * 4 + 0) * 256 + m * 16 + ol]
                + part[(ot * 4 + 1) * 256 + m * 16 + ol]
                + part[(ot * 4 + 2) * 256 + m * 16 + ol]
                + part[(ot * 4 + 3) * 256 + m * 16 + ol] + d_beff[o];
        d_xp[(size_t)(m0 + m) * CC + o] = v;
    }
}

// ---------------- Kernel E: attention, fp16 xf in smem, warp-per-lane --------------
__global__ void kE_attn() {
    __shared__ __half2 xf_s[CC * 125];   // 16000 B (r-pairs)
    __shared__ float xp_s[8 * 64];
    __shared__ float g_buf[8 * 64];
    int b = blockIdx.x, lg = blockIdx.y;
    int tid = threadIdx.x, w = tid >> 5, lid = tid & 31;
    const float4* src = (const float4*)(d_xfh + (size_t)b * (CC * 250));
    for (int i = tid; i < 1000; i += 256) ((float4*)xf_s)[i] = src[i];
    for (int i = tid; i < 512; i += 256) {
        int lane = i >> 6, c = i & 63;
        xp_s[i] = d_xp[(size_t)(b * 64 + lg * 8 + lane) * CC + c];
    }
    __syncthreads();

    const float* xpw = xp_s + w * 64;
    int pr[4]; bool ok[4];
#pragma unroll
    for (int k = 0; k < 4; k++) {
        int p = lid + 32 * k;
        ok[k] = p < 125;
        pr[k] = ok[k] ? p : 124;
    }
    float sx[4] = {0, 0, 0, 0}, sy[4] = {0, 0, 0, 0};
    for (int c = 0; c < 64; c++) {
        float xc = xpw[c];
        const __half2* row = xf_s + c * 125;
#pragma unroll
        for (int k = 0; k < 4; k++) {
            float2 v = __half22float2(row[pr[k]]);
            sx[k] += xc * v.x;
            sy[k] += xc * v.y;
        }
    }
    float mx = -INFINITY;
#pragma unroll
    for (int k = 0; k < 4; k++) {
        sx[k] = ok[k] ? sx[k] * 0.125f : -INFINITY;
        sy[k] = ok[k] ? sy[k] * 0.125f : -INFINITY;
        mx = fmaxf(mx, fmaxf(sx[k], sy[k]));
    }
    mx = warpMaxf(mx);
    float wx[4], wy[4], wsum = 0.f;
#pragma unroll
    for (int k = 0; k < 4; k++) {
        wx[k] = ok[k] ? expf(sx[k] - mx) : 0.f;
        wy[k] = ok[k] ? expf(sy[k] - mx) : 0.f;
        wsum += wx[k] + wy[k];
    }
    wsum = warpSumf(wsum);
    float inv = 1.0f / wsum;
#pragma unroll
    for (int k = 0; k < 4; k++) { wx[k] *= inv; wy[k] *= inv; }

    for (int c = 0; c < 64; c++) {
        const __half2* row = xf_s + c * 125;
        float a = 0.f;
#pragma unroll
        for (int k = 0; k < 4; k++) {
            float2 v = __half22float2(row[pr[k]]);
            a += wx[k] * v.x + wy[k] * v.y;
        }
        a = warpSumf(a);
        if (lid == 0) g_buf[w * 64 + c] = a;
    }
    __syncthreads();
    for (int i = tid; i < 512; i += 256) {
        int lane = i >> 6, c = i & 63;
        d_g[(size_t)(b * 64 + lg * 8 + lane) * CC + c] = g_buf[i];
    }
}

// ---------------- Kernel E3: conv1x1 + relu + residual, per (b, o-group) -----------
__global__ void kE3_out(const float* __restrict__ w1x1, const float* __restrict__ b1x1,
                        const float* __restrict__ prior, float* __restrict__ out) {
    __shared__ float g_s[4096];
    __shared__ float gr_s[8];
    int b = blockIdx.x, og = blockIdx.y;
    int tid = threadIdx.x, w = tid >> 5, lid = tid & 31;
    const float4* gsrc = (const float4*)(d_g + (size_t)b * 4096);
    for (int i = tid; i < 1024; i += 256) ((float4*)g_s)[i] = gsrc[i];
    __syncthreads();
    int o = og * 8 + w;
    const float4* wr = (const float4*)(w1x1 + (size_t)o * 4096);
    float a = 0.f;
#pragma unroll 4
    for (int j4 = lid; j4 < 1024; j4 += 32) {
        float4 wv = wr[j4];
        float4 gv = ((const float4*)g_s)[j4];
        a += wv.x * gv.x + wv.y * gv.y + wv.z * gv.z + wv.w * gv.w;
    }
    a = warpSumf(a);
    if (lid == 0) gr_s[w] = fmaxf(a + b1x1[o], 0.f);
    __syncthreads();
    for (int e = tid; e < 8 * PE; e += 256) {
        int jl = e / PE, t = e - jl * PE;
        size_t idx = (size_t)b * (64 * PE) + (size_t)(og * 8 + jl) * PE + t;
        out[idx] = gr_s[jl] + prior[idx];
    }
}

// ---------------- host launcher ----------------------------------------------------
extern "C" void kernel_launch(void* const* d_in, const int* in_sizes, int n_in,
                              void* d_out, int out_size) {
    const float* feature = (const float*)d_in[0];
    const float* prior   = (const float*)d_in[1];
    const float* w1      = (const float*)d_in[2];
    const float* b1      = (const float*)d_in[3];
    const float* fw      = (const float*)d_in[4];
    const float* fb      = (const float*)d_in[5];
    const float* w1x1    = (const float*)d_in[6];
    const float* b1x1    = (const float*)d_in[7];
    float* out = (float*)d_out;

    cudaFuncSetAttribute(kD_xp, cudaFuncAttributeMaxDynamicSharedMemorySize,
                         16 * 2304 * 2 + 16384);

    kA_transpose_pool<<<dim3(500, 2, BB), dim3(32, 8)>>>(feature);
    kA2_pool_reduce<<<dim3(250, BB), 64>>>();
    kC_fold<<<dim3(CC, 8), 256>>>(w1, b1, fw);
    kC2_reduce<<<dim3(36, 8), 256>>>(fb);
    kD_xp<<<M_TOT / 16, 512, 16 * 2304 * 2 + 16384>>>(prior);
    kE_attn<<<dim3(BB, 8), 256>>>();
    kE3_out<<<dim3(BB, 8), 256>>>(w1x1, b1x1, prior, out);
}

// round 6
// speedup vs baseline: 2.7830x; 1.0850x over previous
#include <cuda_runtime.h>
#include <cuda_fp16.h>
#include <mma.h>
#include <math.h>

using namespace nvcuda;

#define BB 32
#define CC 64
#define FH 80
#define FW 200
#define HW 16000
#define LANES 64
#define SP 36
#define PE 78
#define J_TOT 2304
#define M_TOT 2048

// ---------------- scratch ----------------
__device__ __half d_featT[BB * HW * CC];          // (B,H,W,C) fp16
__device__ float  d_pool8[BB * 2000 * CC];        // partial pool [b][q][c]
__device__ __half d_xfh[BB * CC * 250];           // pooled context fp16 [b][c][r]
__device__ float  d_weffp[8 * CC * J_TOT];        // fold partials [ck][o][j]
__device__ float  d_beffp[CC * 8];
__device__ __half d_weffh[J_TOT * CC];            // folded weight fp16 [j][o]
__device__ float  d_beff[CC];
__device__ float  d_g[M_TOT * CC];                // attention output [m][c]

__device__ __forceinline__ float warpMaxf(float a) {
#pragma unroll
    for (int off = 16; off > 0; off >>= 1) a = fmaxf(a, __shfl_xor_sync(0xffffffffu, a, off));
    return a;
}
__device__ __forceinline__ float warpSumf(float a) {
#pragma unroll
    for (int off = 16; off > 0; off >>= 1) a += __shfl_xor_sync(0xffffffffu, a, off);
    return a;
}

// ---------------- Kernel A: transpose (B,C,H,W)->(B,H,W,C) fp16 + fused pool --------
// block = 64c x 64hw tile, 256 threads, grid (250, B)
__global__ void kA_transpose_pool(const float* __restrict__ feat) {
    __shared__ float tile[64][65];
    int bx = blockIdx.x, b = blockIdx.y;
    int tid = threadIdx.x;
    const float4* src = (const float4*)(feat + (size_t)b * CC * HW + bx * 64);
#pragma unroll
    for (int i = tid; i < 1024; i += 256) {
        int c = i >> 4, x4 = i & 15;
        float4 v = src[(size_t)c * (HW / 4) + x4];
        tile[c][x4 * 4 + 0] = v.x; tile[c][x4 * 4 + 1] = v.y;
        tile[c][x4 * 4 + 2] = v.z; tile[c][x4 * 4 + 3] = v.w;
    }
    __syncthreads();
    // write featT: 64 hw-rows x 64 c fp16; 8 threads x 16B per row
#pragma unroll
    for (int i = tid; i < 512; i += 256) {
        int row = i >> 3, seg = i & 7;
        __align__(16) __half h[8];
#pragma unroll
        for (int j = 0; j < 8; j++) h[j] = __float2half_rn(tile[seg * 8 + j][row]);
        *(uint4*)(d_featT + ((size_t)b * HW + bx * 64 + row) * CC + seg * 8) = *(uint4*)h;
    }
    // pool partials: q = hw/8 (8 q per block), coalesced over c
#pragma unroll
    for (int i = tid; i < 512; i += 256) {
        int q = i >> 6, c = i & 63;
        float s = 0.f;
#pragma unroll
        for (int j = 0; j < 8; j++) s += tile[c][q * 8 + j];
        d_pool8[((size_t)b * 2000 + bx * 8 + q) * CC + c] = s;
    }
}

// ---------------- Kernel A2: reduce 8 h-rows -> d_xfh (fp16) -----------------------
__global__ void kA2_pool_reduce() {
    int r = blockIdx.x, b = blockIdx.y, c = threadIdx.x;
    int rh = r / 25, rw = r - rh * 25;
    float acc = 0.f;
#pragma unroll
    for (int dh = 0; dh < 8; dh++)
        acc += d_pool8[((size_t)b * 2000 + (rh * 8 + dh) * 25 + rw) * CC + c];
    d_xfh[((size_t)b * CC + c) * 250 + r] = __float2half_rn(acc * (1.0f / 64.0f));
}

// ---------------- Kernel C: fold conv1d+fc partials, layout [ck][o][j] -------------
__global__ void kC_fold(const float* __restrict__ w1, const float* __restrict__ b1,
                        const float* __restrict__ fw) {
    __shared__ float fc_s[256];
    __shared__ float red[256];
    int o = blockIdx.x, ck = blockIdx.y;
    int cmBase = ck * 8;
    int tid = threadIdx.x;
    fc_s[tid] = fw[o * 2048 + cmBase * 32 + tid];
    __syncthreads();
    int cin = tid & 63, s0 = tid >> 6;
    float acc[9];
#pragma unroll
    for (int it = 0; it < 9; it++) acc[it] = 0.f;
#pragma unroll
    for (int cm8 = 0; cm8 < 8; cm8++) {
        int cm = cmBase + cm8;
        float wv[5];
#pragma unroll
        for (int k = 0; k < 5; k++) wv[k] = __ldg(w1 + (cm * CC + cin) * 5 + k);
        const float* frow = fc_s + cm8 * 32;
#pragma unroll
        for (int it = 0; it < 9; it++) {
            int s = s0 + it * 4;
#pragma unroll
            for (int k = 0; k < 5; k++) {
                int t = s - k;
                if ((unsigned)t < 32u) acc[it] += frow[t] * wv[k];
            }
        }
    }
#pragma unroll
    for (int it = 0; it < 9; it++)
        d_weffp[(size_t)ck * (CC * J_TOT) + (size_t)o * J_TOT + (tid + it * 256)] = acc[it];
    red[tid] = fc_s[tid] * b1[cmBase + (tid >> 5)];
    __syncthreads();
    for (int st = 128; st > 0; st >>= 1) {
        if (tid < st) red[tid] += red[tid + st];
        __syncthreads();
    }
    if (tid == 0) d_beffp[o * 8 + ck] = red[0];
}

// ---------------- Kernel C2: reduce partials + transpose -> fp16 [j][o] ------------
__global__ void kC2_reduce(const float* __restrict__ fb) {
    __shared__ float t_s[64][9];
    int jb = blockIdx.x, og = blockIdx.y;
    int tid = threadIdx.x;
#pragma unroll
    for (int i = tid; i < 512; i += 256) {
        int ol = i >> 6, jl = i & 63;
        float a = 0.f;
#pragma unroll
        for (int ck = 0; ck < 8; ck++)
            a += d_weffp[(size_t)ck * (CC * J_TOT) + (size_t)(og * 8 + ol) * J_TOT + jb * 64 + jl];
        t_s[jl][ol] = a;
    }
    __syncthreads();
    {
        int jl = tid >> 2, op = tid & 3;
        __half2 h = __floats2half2_rn(t_s[jl][2 * op], t_s[jl][2 * op + 1]);
        ((__half2*)d_weffh)[(size_t)(jb * 64 + jl) * 32 + og * 4 + op] = h;
    }
    if (jb == 0 && og == 0 && tid < CC) {
        float s = 0.f;
#pragma unroll
        for (int ck = 0; ck < 8; ck++) s += d_beffp[tid * 8 + ck];
        d_beff[tid] = fb[tid] + s;
    }
}

// ---------------- Kernel DE: gather + wmma x_p + attention, fused ------------------
// 256 blocks, 256 threads (8 warps). Block = 8 m's = one (b, lane-group).
// dyn smem: rs 36864 | part 8192 | xf 32000  = 77056 B
__global__ void kDE(const float* __restrict__ prior) {
    extern __shared__ char smraw[];
    __half* rs = (__half*)smraw;                           // 8*2304*2 = 36864 B
    float* part = (float*)(smraw + 36864);                 // 8*256 f = 8192 B
    __half2* xf_s = (__half2*)(smraw + 36864 + 8192);      // 64*125 half2 = 32000 B
    __shared__ int offs0[288], offs1[288], offs2[288], offs3[288];
    __shared__ float xp_s[8 * 64];
    __shared__ float g_buf[8 * 64];

    int m0 = blockIdx.x * 8;
    int b = m0 >> 6;
    int tid = threadIdx.x;
    int w = tid >> 5, lane = tid & 31;

    // full xf slice: 64c x 250r fp16 = 32000 B = 2000 float4 (issued early, overlaps gather)
    const float4* xsrc = (const float4*)(d_xfh + (size_t)b * (CC * 250));
#pragma unroll
    for (int i = tid; i < 2000; i += 256) ((float4*)xf_s)[i] = xsrc[i];

    // coordinates -> offsets for 8 m x 36 s
    for (int i = tid; i < 288; i += 256) {
        int ml = i / 36, s = i - ml * 36;
        float px = prior[(size_t)(m0 + ml) * PE + 6 + 2 * s];
        float xs = fminf(px * 0.25f, 199.0f);
        int xc = (int)ceilf(xs), xf_ = (int)floorf(xs);
        double py = 319.0 - (320.0 / 71.0) * (double)(2 * s);
        float ys = fminf((float)py * 0.25f, 79.0f);
        int yc = (int)ceilf(ys), yf_ = (int)floorf(ys);
        offs0[i] = (yc * FW + xc) * CC;
        offs1[i] = (yc * FW + xf_) * CC;
        offs2[i] = (yf_ * FW + xc) * CC;
        offs3[i] = (yf_ * FW + xf_) * CC;
    }
    __syncthreads();

    // gather: warp per point-quad, lane = channel-pair
    const __half2* f2 = (const __half2*)(d_featT + (size_t)b * HW * CC);
    __half2* rs2 = (__half2*)rs;
#pragma unroll 2
    for (int i = w; i < 288; i += 8) {
        int ml = i / 36, s = i - ml * 36;
        float2 v0 = __half22float2(f2[(offs0[i] >> 1) + lane]);
        float2 v1 = __half22float2(f2[(offs1[i] >> 1) + lane]);
        float2 v2 = __half22float2(f2[(offs2[i] >> 1) + lane]);
        float2 v3 = __half22float2(f2[(offs3[i] >> 1) + lane]);
        float2 r;
        r.x = (v0.x + v1.x + v2.x + v3.x) * 0.25f;
        r.y = (v0.y + v1.y + v2.y + v3.y) * 0.25f;
        rs2[((ml * J_TOT + s * CC) >> 1) + lane] = __float22half2_rn(r);
    }
    __syncthreads();

    // wmma m8n32k16: warp w -> otile = w>>2 (32 o's), kq = w&3 (36 ksteps)
    {
        int otile = w >> 2, kq = w & 3;
        wmma::fragment<wmma::matrix_a, 8, 32, 16, __half, wmma::row_major> af;
        wmma::fragment<wmma::matrix_b, 8, 32, 16, __half, wmma::row_major> bf;
        wmma::fragment<wmma::accumulator, 8, 32, 16, float> cf;
        wmma::fill_fragment(cf, 0.0f);
        for (int ks = kq * 36; ks < kq * 36 + 36; ks++) {
            int k0 = ks * 16;
            wmma::load_matrix_sync(af, rs + k0, J_TOT);
            wmma::load_matrix_sync(bf, d_weffh + (size_t)k0 * CC + otile * 32, CC);
            wmma::mma_sync(cf, af, bf, cf);
        }
        wmma::store_matrix_sync(part + w * 256, cf, 32, wmma::mem_row_major);
    }
    __syncthreads();

    // combine k-quarters + bias -> xp_s[m][o]
    for (int i = tid; i < 512; i += 256) {
        int m = i >> 6, o = i & 63;
        int ot = o >> 5, ol = o & 31;
        float v = part[(ot * 4 + 0) * 256 + m * 32 + ol]
                + part[(ot * 4 + 1) * 256 + m * 32 + ol]
                + part[(ot * 4 + 2) * 256 + m * 32 + ol]
                + part[(ot * 4 + 3) * 256 + m * 32 + ol] + d_beff[o];
        xp_s[i] = v;
    }
    __syncthreads();

    // attention: warp w handles m = m0 + w
    const float* xpw = xp_s + w * 64;
    int pr[4]; bool ok[4];
#pragma unroll
    for (int k = 0; k < 4; k++) {
        int p = lane + 32 * k;
        ok[k] = p < 125;
        pr[k] = ok[k] ? p : 124;
    }
    float sx[4] = {0, 0, 0, 0}, sy[4] = {0, 0, 0, 0};
    for (int c = 0; c < 64; c++) {
        float xc = xpw[c];
        const __half2* row = xf_s + c * 125;
#pragma unroll
        for (int k = 0; k < 4; k++) {
            float2 v = __half22float2(row[pr[k]]);
            sx[k] += xc * v.x;
            sy[k] += xc * v.y;
        }
    }
    float mx = -INFINITY;
#pragma unroll
    for (int k = 0; k < 4; k++) {
        sx[k] = ok[k] ? sx[k] * 0.125f : -INFINITY;
        sy[k] = ok[k] ? sy[k] * 0.125f : -INFINITY;
        mx = fmaxf(mx, fmaxf(sx[k], sy[k]));
    }
    mx = warpMaxf(mx);
    float wx[4], wy[4], wsum = 0.f;
#pragma unroll
    for (int k = 0; k < 4; k++) {
        wx[k] = ok[k] ? expf(sx[k] - mx) : 0.f;
        wy[k] = ok[k] ? expf(sy[k] - mx) : 0.f;
        wsum += wx[k] + wy[k];
    }
    wsum = warpSumf(wsum);
    float inv = 1.0f / wsum;
#pragma unroll
    for (int k = 0; k < 4; k++) { wx[k] *= inv; wy[k] *= inv; }

    for (int c = 0; c < 64; c++) {
        const __half2* row = xf_s + c * 125;
        float a = 0.f;
#pragma unroll
        for (int k = 0; k < 4; k++) {
            float2 v = __half22float2(row[pr[k]]);
            a += wx[k] * v.x + wy[k] * v.y;
        }
        a = warpSumf(a);
        if (lane == 0) g_buf[w * 64 + c] = a;
    }
    __syncthreads();
    for (int i = tid; i < 512; i += 256) {
        int ml = i >> 6, c = i & 63;
        d_g[(size_t)(m0 + ml) * CC + c] = g_buf[i];
    }
}

// ---------------- Kernel E3: conv1x1 + relu + residual, per (b, o-group) -----------
__global__ void kE3_out(const float* __restrict__ w1x1, const float* __restrict__ b1x1,
                        const float* __restrict__ prior, float* __restrict__ out) {
    __shared__ float g_s[4096];
    __shared__ float gr_s[8];
    int b = blockIdx.x, og = blockIdx.y;
    int tid = threadIdx.x, w = tid >> 5, lid = tid & 31;
    const float4* gsrc = (const float4*)(d_g + (size_t)b * 4096);
    for (int i = tid; i < 1024; i += 256) ((float4*)g_s)[i] = gsrc[i];
    __syncthreads();
    int o = og * 8 + w;
    const float4* wr = (const float4*)(w1x1 + (size_t)o * 4096);
    float a = 0.f;
#pragma unroll 4
    for (int j4 = lid; j4 < 1024; j4 += 32) {
        float4 wv = wr[j4];
        float4 gv = ((const float4*)g_s)[j4];
        a += wv.x * gv.x + wv.y * gv.y + wv.z * gv.z + wv.w * gv.w;
    }
    a = warpSumf(a);
    if (lid == 0) gr_s[w] = fmaxf(a + b1x1[o], 0.f);
    __syncthreads();
    for (int e = tid; e < 8 * PE; e += 256) {
        int jl = e / PE, t = e - jl * PE;
        size_t idx = (size_t)b * (64 * PE) + (size_t)(og * 8 + jl) * PE + t;
        out[idx] = gr_s[jl] + prior[idx];
    }
}

// ---------------- host launcher ----------------------------------------------------
extern "C" void kernel_launch(void* const* d_in, const int* in_sizes, int n_in,
                              void* d_out, int out_size) {
    const float* feature = (const float*)d_in[0];
    const float* prior   = (const float*)d_in[1];
    const float* w1      = (const float*)d_in[2];
    const float* b1      = (const float*)d_in[3];
    const float* fw      = (const float*)d_in[4];
    const float* fb      = (const float*)d_in[5];
    const float* w1x1    = (const float*)d_in[6];
    const float* b1x1    = (const float*)d_in[7];
    float* out = (float*)d_out;

    const int kde_smem = 36864 + 8192 + 32000;   // rs | part | xf  = 77056 B
    cudaFuncSetAttribute(kDE, cudaFuncAttributeMaxDynamicSharedMemorySize, kde_smem);

    kA_transpose_pool<<<dim3(250, BB), 256>>>(feature);
    kA2_pool_reduce<<<dim3(250, BB), 64>>>();
    kC_fold<<<dim3(CC, 8), 256>>>(w1, b1, fw);
    kC2_reduce<<<dim3(36, 8), 256>>>(fb);
    kDE<<<M_TOT / 8, 256, kde_smem>>>(prior);
    kE3_out<<<dim3(BB, 8), 256>>>(w1x1, b1x1, prior, out);
}